// round 3
// baseline (speedup 1.0000x reference)
#include <cuda_runtime.h>
#include <stdint.h>

#define N_PTS   50000
#define B_ROWS  512
#define E_DIM   16
#define KSEL    20
#define TILE    512
#define G_ROWS  8
#define NBLOCKS 128          // (B_ROWS/G_ROWS) * 2 sets
#define HID     64
#define FULLM   0xffffffffu

typedef unsigned long long ull;

__device__ float g_feats[B_ROWS][8];
__device__ int   g_done = 0;

static __device__ __forceinline__ float finf() { return __int_as_float(0x7f800000); }

// ---- packed f32x2 helpers (PTX-only) ----
static __device__ __forceinline__ ull pk2(float lo, float hi) {
    ull r; asm("mov.b64 %0,{%1,%2};" : "=l"(r) : "f"(lo), "f"(hi)); return r;
}
static __device__ __forceinline__ void upk2(ull v, float& lo, float& hi) {
    asm("mov.b64 {%0,%1},%2;" : "=f"(lo), "=f"(hi) : "l"(v));
}
static __device__ __forceinline__ ull fma2(ull a, ull b, ull c) {
    ull d; asm("fma.rn.f32x2 %0,%1,%2,%3;" : "=l"(d) : "l"(a), "l"(b), "l"(c)); return d;
}
static __device__ __forceinline__ ull add2(ull a, ull b) {
    ull d; asm("add.rn.f32x2 %0,%1,%2;" : "=l"(d) : "l"(a), "l"(b)); return d;
}

// ---------------------------------------------------------------------------
// Fused kernel: distances + top-20 + features, MLP in a tail block.
//   grid = (64, 2 sets), block = 512 (16 warps).
//   Queries live in SMEM (pre-scaled by -2, k-packed f32x2); Phase A streams
//   candidates through registers, 64 FFMA2 + 32 LDS.128 per thread per tile.
//   Warp pair (w, w+8) owns row w&7; each scans half of the 512-wide tile.
// ---------------------------------------------------------------------------
__global__ __launch_bounds__(512, 1)
void knn_kernel(const float* __restrict__ emb0, const float* __restrict__ emb1,
                const float* __restrict__ rctx0, const float* __restrict__ rctx1,
                const int* __restrict__ idx0, const int* __restrict__ idx1,
                const float* __restrict__ mean_in, const float* __restrict__ std_in,
                const float* __restrict__ W1, const float* __restrict__ b1,
                const float* __restrict__ Wm, const float* __restrict__ bm,
                const float* __restrict__ Ws, const float* __restrict__ bs,
                float* __restrict__ out, int n) {
    const int set = blockIdx.y;
    const float* __restrict__ emb  = set ? emb1 : emb0;
    const float* __restrict__ rctx = set ? rctx1 : rctx0;
    const int*   __restrict__ idxp = set ? idx1 : idx0;

    const int rowbase = blockIdx.x * G_ROWS;
    const int tid  = threadIdx.x;
    const int lane = tid & 31;
    const int w    = tid >> 5;          // 0..15
    const int rloc = w & 7;             // local row this warp scans
    const int half = w >> 3;            // which half of the tile

    __shared__ ull   q_sm[8][8];        // [c][r] : pack(-2q[r][2c], -2q[r][2c+1])
    __shared__ float na_sm[8];
    __shared__ int   self_sm[8];
    __shared__ float sbuf[2][TILE][9];  // pad 9 -> conflict-free
    __shared__ float mval[8][KSEL];
    __shared__ int   midx[8][KSEL];
    __shared__ int   lastflag;

    // ---- stage queries: warp r handles row r ----
    if (w < G_ROWS) {
        int si = 0;
        if (lane == 0) si = idxp[rowbase + w];
        si = __shfl_sync(FULLM, si, 0);
        if (lane == 0) self_sm[w] = si;
        float nx = 0.f;
        if (lane < 8) {
            float2 v = reinterpret_cast<const float2*>(emb + (size_t)si * E_DIM)[lane];
            nx = v.x * v.x + v.y * v.y;
            q_sm[lane][w] = pk2(-2.f * v.x, -2.f * v.y);
        }
        nx += __shfl_xor_sync(FULLM, nx, 4);
        nx += __shfl_xor_sync(FULLM, nx, 2);
        nx += __shfl_xor_sync(FULLM, nx, 1);
        if (lane == 0) na_sm[w] = nx;
    }

    // ---- top-k state (lanes 0..19 ascending) ----
    float kval   = finf();
    int   kidx   = -1;
    float thresh = finf();

    auto insert = [&](float bv, int bj) {
        float pv = __shfl_up_sync(FULLM, kval, 1);
        int   pj = __shfl_up_sync(FULLM, kidx, 1);
        if (lane < KSEL && bv < kval) {
            if (lane == 0 || bv >= pv) { kval = bv; kidx = bj; }
            else                        { kval = pv; kidx = pj; }
        }
        thresh = __shfl_sync(FULLM, kval, KSEL - 1);
    };

    const int ntiles = (n + TILE - 1) / TILE;   // 98

    ull eA[8], eB[8];
    auto loadTile = [&](int t, ull* e2) {
        int j = t * TILE + tid;
        if (j < n) {
            const ulonglong2* ep =
                reinterpret_cast<const ulonglong2*>(emb + (size_t)j * E_DIM);
            ulonglong2 a = ep[0], b = ep[1], c = ep[2], d = ep[3];
            e2[0] = a.x; e2[1] = a.y; e2[2] = b.x; e2[3] = b.y;
            e2[4] = c.x; e2[5] = c.y; e2[6] = d.x; e2[7] = d.y;
        }
    };

    auto phaseA = [&](int t, int buf, ull* e2) {
        bool valid = (t * TILE + tid) < n;
        ull nA = pk2(0.f, 0.f), nB = pk2(0.f, 0.f);
#pragma unroll
        for (int c = 0; c < 8; c += 2) {
            nA = fma2(e2[c],     e2[c],     nA);
            nB = fma2(e2[c + 1], e2[c + 1], nB);
        }
        ull nrm2 = add2(nA, nB);
        ull acc[G_ROWS];
#pragma unroll
        for (int r = 0; r < G_ROWS; r++) acc[r] = nrm2;
#pragma unroll
        for (int c = 0; c < 8; c++) {
            ull ec = e2[c];
#pragma unroll
            for (int p = 0; p < 4; p++) {
                ulonglong2 qp = *reinterpret_cast<const ulonglong2*>(&q_sm[c][2 * p]);
                acc[2 * p]     = fma2(qp.x, ec, acc[2 * p]);
                acc[2 * p + 1] = fma2(qp.y, ec, acc[2 * p + 1]);
            }
        }
#pragma unroll
        for (int r = 0; r < G_ROWS; r++) {
            float lo, hi; upk2(acc[r], lo, hi);
            sbuf[buf][tid][r] = valid ? (lo + hi) : finf();
        }
    };

    const int myself = self_sm[rloc];   // valid after first __syncthreads below

    auto phaseB = [&](int t, int buf, int self) {
        const int base = t * TILE + half * 256;
        float v[8];
#pragma unroll
        for (int i = 0; i < 8; i++) v[i] = sbuf[buf][half * 256 + lane + 32 * i][rloc];
        unsigned hm = 0;
#pragma unroll
        for (int i = 0; i < 8; i++) {
            int j = base + lane + 32 * i;
            if (v[i] < thresh && j != self) hm |= (1u << i);
        }
        unsigned red = __reduce_or_sync(FULLM, hm);
        while (red) {
            int i = __ffs(red) - 1; red &= red - 1;
            unsigned m = __ballot_sync(FULLM, (hm >> i) & 1u);
            float vi = v[i];
            int   ji = base + lane + 32 * i;
            while (m) {
                int src = __ffs(m) - 1; m &= m - 1;
                float bv = __shfl_sync(FULLM, vi, src);
                int   bj = __shfl_sync(FULLM, ji, src);
                if (bv < thresh) insert(bv, bj);
            }
        }
    };

    loadTile(0, eA);
    __syncthreads();                 // q_sm / self_sm ready
    const int selfi = self_sm[rloc];

    for (int t = 0; t < ntiles; t += 2) {
        loadTile(t + 1, eB);
        phaseA(t, 0, eA);
        __syncthreads();
        phaseB(t, 0, selfi);
        loadTile(t + 2, eA);         // harmless OOB-guarded when t+2==ntiles
        phaseA(t + 1, 1, eB);
        __syncthreads();
        phaseB(t + 1, 1, selfi);
    }

    // ---- merge the two half-lists per row ----
    if (half == 1 && lane < KSEL) {
        mval[rloc][lane] = kval;
        midx[rloc][lane] = kidx;
    }
    __syncthreads();
    if (half == 0) {
#pragma unroll 1
        for (int tmerge = 0; tmerge < KSEL; tmerge++) {
            float bv = mval[rloc][tmerge];
            int   bj = midx[rloc][tmerge];
            if (bv < thresh) insert(bv, bj);
        }
        // ---- features for row (rowbase + rloc) ----
        const int row = rowbase + rloc;
        float na = na_sm[rloc];
        float wgt = 0.f, sel = 0.f;
        if (lane < KSEL) {
            float d2  = fmaxf(kval + na, 0.f);
            float sim = sqrtf(d2) + 0.001f;
            wgt = __expf(-sim);
            sel = rctx[(size_t)row * n + kidx];
        }
        float sw = wgt, ssw = sel * wgt, ss = sel, ss2 = sel * sel;
#pragma unroll
        for (int off = 16; off; off >>= 1) {
            sw  += __shfl_xor_sync(FULLM, sw,  off);
            ssw += __shfl_xor_sync(FULLM, ssw, off);
            ss  += __shfl_xor_sync(FULLM, ss,  off);
            ss2 += __shfl_xor_sync(FULLM, ss2, off);
        }
        if (lane == 0) {
            float f1 = sw;
            float f2 = ssw / sw;
            float var = (ss2 - ss * ss / (float)KSEL) / (float)(KSEL - 1);
            float f3 = sqrtf(fmaxf(var, 0.f));
            g_feats[row][0 + set] = f1;
            g_feats[row][2 + set] = f2;
            g_feats[row][4 + set] = f3;
        }
    }

    // ---- tail block runs the MLP ----
    __threadfence();
    __syncthreads();
    if (tid == 0) {
        int c = atomicAdd(&g_done, 1);
        lastflag = (c == NBLOCKS - 1);
    }
    __syncthreads();
    if (!lastflag) return;
    __threadfence();

    {
        int r = tid;                 // 512 threads, 512 rows
        float f[8];
#pragma unroll
        for (int i = 0; i < 6; i++) f[i] = g_feats[r][i];
        f[6] = mean_in[r];
        f[7] = std_in[r];
        float m = bm[0], sd = bs[0];
#pragma unroll 4
        for (int j = 0; j < HID; j++) {
            float h = b1[j];
#pragma unroll
            for (int i = 0; i < 8; i++) h = fmaf(f[i], W1[i * HID + j], h);
            h = fmaxf(h, 0.f);
            m  = fmaf(h, Wm[j], m);
            sd = fmaf(h, Ws[j], sd);
        }
        out[r]          = m;
        out[B_ROWS + r] = sd;
    }
    if (tid == 0) g_done = 0;        // re-arm for next (graph) launch
}

// ---------------------------------------------------------------------------
extern "C" void kernel_launch(void* const* d_in, const int* in_sizes, int n_in,
                              void* d_out, int out_size) {
    const float* emb0    = (const float*)d_in[0];
    const float* emb1    = (const float*)d_in[1];
    const float* rctx0   = (const float*)d_in[2];
    const float* rctx1   = (const float*)d_in[3];
    const int*   idx0    = (const int*)  d_in[4];
    const int*   idx1    = (const int*)  d_in[5];
    const float* mean_in = (const float*)d_in[6];
    const float* std_in  = (const float*)d_in[7];
    const float* W1      = (const float*)d_in[8];
    const float* b1      = (const float*)d_in[9];
    const float* Wm      = (const float*)d_in[10];
    const float* bm      = (const float*)d_in[11];
    const float* Ws      = (const float*)d_in[12];
    const float* bs      = (const float*)d_in[13];

    int n = in_sizes[0] / E_DIM;    // 50000

    dim3 grid(B_ROWS / G_ROWS, 2);
    knn_kernel<<<grid, TILE>>>(emb0, emb1, rctx0, rctx1, idx0, idx1,
                               mean_in, std_in, W1, b1, Wm, bm, Ws, bs,
                               (float*)d_out, n);
}